// round 1
// baseline (speedup 1.0000x reference)
#include <cuda_runtime.h>
#include <math.h>

#define BIGV   100000000.0f
#define GAMMA_ 0.05f
#define INVG_  20.0f
#define WARPP  256.0f
#define K_     4
#define B_     8
#define KB_    32
#define N_     800
#define C_     80
#define S_     128
#define Z_     32

// ---- scratch (device globals; no runtime allocation) ----
__device__ float g_sx[(size_t)KB_ * N_ * C_];   // sigmoid(mel_iters)
__device__ float g_sy[(size_t)B_  * N_ * C_];   // sigmoid(mel_targets)
__device__ float g_x2[KB_ * N_];                // row norms of sx
__device__ float g_y2[B_  * N_];                // row norms of sy
__device__ float g_D [(size_t)KB_ * N_ * N_];   // distance matrices
__device__ float g_d [KB_];                     // DTW costs

// ============================================================
// Kernel 1: sigmoid + squared row norms. One warp per row.
// ============================================================
__global__ void prep_kernel(const float* __restrict__ mel_iters,
                            const float* __restrict__ mel_targets) {
    int wid  = (blockIdx.x * blockDim.x + threadIdx.x) >> 5;
    int lane = threadIdx.x & 31;
    const int xrows = KB_ * N_;
    const int total = xrows + B_ * N_;
    if (wid >= total) return;

    const float* src;
    float* dst;
    float* nrm;
    if (wid < xrows) {
        src = mel_iters + (size_t)wid * C_;
        dst = g_sx      + (size_t)wid * C_;
        nrm = g_x2 + wid;
    } else {
        int r = wid - xrows;
        src = mel_targets + (size_t)r * C_;
        dst = g_sy        + (size_t)r * C_;
        nrm = g_y2 + r;
    }
    float acc = 0.f;
    for (int c = lane; c < C_; c += 32) {
        float v = src[c];
        float s = 1.f / (1.f + expf(-v));
        dst[c] = s;
        acc += s * s;
    }
    #pragma unroll
    for (int o = 16; o; o >>= 1) acc += __shfl_xor_sync(0xffffffffu, acc, o);
    if (lane == 0) *nrm = acc;
}

// ============================================================
// Kernel 2: D[kb][n][m] = x2[n] + y2[m] - 2 * <sx[n], sy[m]>
// 64x64 output tile per CTA, K=80, 256 threads, 4x4 microtile.
// Shared tiles stored transposed ([c][row], pad 65) for
// conflict-free compute-phase LDS.
// ============================================================
__global__ void __launch_bounds__(256) dist_gemm_kernel() {
    __shared__ float sA[80 * 65];   // sA[c*65 + local_n]
    __shared__ float sB[80 * 65];   // sB[c*65 + local_m]

    const int kb = blockIdx.z;
    const int b  = kb & 7;
    const int m0 = blockIdx.x * 64;
    const int n0 = blockIdx.y * 64;
    const int t  = threadIdx.x;

    const float* xbase = g_sx + (size_t)kb * N_ * C_ + (size_t)n0 * C_;
    const float* ybase = g_sy + (size_t)b  * N_ * C_ + (size_t)m0 * C_;

    // Load 64x80 tiles (coalesced reads, padded transposed smem writes)
    for (int e = t; e < 64 * 80; e += 256) {
        int r = e / 80;
        int c = e - r * 80;
        float xv = (n0 + r < N_) ? xbase[r * C_ + c] : 0.f;
        float yv = (m0 + r < N_) ? ybase[r * C_ + c] : 0.f;
        sA[c * 65 + r] = xv;
        sB[c * 65 + r] = yv;
    }
    __syncthreads();

    const int tx = t & 15;   // m microtile
    const int ty = t >> 4;   // n microtile

    float acc[4][4];
    #pragma unroll
    for (int i = 0; i < 4; i++)
        #pragma unroll
        for (int j = 0; j < 4; j++) acc[i][j] = 0.f;

    #pragma unroll 8
    for (int k = 0; k < 80; k++) {
        float a[4], bb[4];
        #pragma unroll
        for (int i = 0; i < 4; i++) a[i]  = sA[k * 65 + ty * 4 + i];
        #pragma unroll
        for (int j = 0; j < 4; j++) bb[j] = sB[k * 65 + tx * 4 + j];
        #pragma unroll
        for (int i = 0; i < 4; i++)
            #pragma unroll
            for (int j = 0; j < 4; j++)
                acc[i][j] = fmaf(a[i], bb[j], acc[i][j]);
    }

    float* Dp = g_D + (size_t)kb * N_ * N_;
    #pragma unroll
    for (int i = 0; i < 4; i++) {
        int n = n0 + ty * 4 + i;
        if (n >= N_) continue;
        float xn = g_x2[kb * N_ + n];
        int mbase = m0 + tx * 4;
        if (mbase + 3 < N_) {
            float4 v;
            v.x = xn + g_y2[b * N_ + mbase + 0] - 2.f * acc[i][0];
            v.y = xn + g_y2[b * N_ + mbase + 1] - 2.f * acc[i][1];
            v.z = xn + g_y2[b * N_ + mbase + 2] - 2.f * acc[i][2];
            v.w = xn + g_y2[b * N_ + mbase + 3] - 2.f * acc[i][3];
            *reinterpret_cast<float4*>(&Dp[(size_t)n * N_ + mbase]) = v;
        } else {
            #pragma unroll
            for (int j = 0; j < 4; j++) {
                int m = mbase + j;
                if (m < N_)
                    Dp[(size_t)n * N_ + m] = xn + g_y2[b * N_ + m] - 2.f * acc[i][j];
            }
        }
    }
}

// ============================================================
// Kernel 3: soft-DTW anti-diagonal wavefront. 1 CTA per pair,
// 800 threads (thread t handles row i = t+1). Rolling 3 rows in
// smem. Softmin short-circuits to min when the second-smallest
// arm exceeds min by > 1.0 (then fp32 logsumexp is exactly min,
// matching the reference bit-for-bit in those cells).
// ============================================================
__global__ void __launch_bounds__(800) dtw_kernel() {
    __shared__ float buf[3][N_ + 1];
    const int kb = blockIdx.x;
    const int t  = threadIdx.x;
    const int i  = t + 1;

    for (int idx = t; idx <= N_; idx += 800) {
        buf[0][idx] = BIGV;
        buf[1][idx] = BIGV;
        buf[2][idx] = BIGV;
    }
    if (t == 0) buf[0][0] = 0.f;
    __syncthreads();

    float* two = buf[0];
    float* one = buf[1];
    float* nw  = buf[2];

    const float* Drow = g_D + (size_t)kb * N_ * N_ + (size_t)(i - 1) * N_ - 1;

    float res = 0.f;
    for (int d = 2; d <= 2 * N_; d++) {
        int j = d - i;
        float r = BIGV;
        if (j >= 1 && j <= N_) {
            float a = two[i - 1];
            float b = one[i - 1] + WARPP;
            float c = one[i]     + WARPP;
            float m = fminf(a, fminf(b, c));
            float sm = m;
            float d1 = a - m, d2 = b - m, d3 = c - m;
            // second-smallest delta = d1+d2+d3 - max (smallest is 0)
            float second = d1 + d2 + d3 - fmaxf(d1, fmaxf(d2, d3));
            if (second < 1.0f) {
                sm = m - GAMMA_ * logf(expf(-d1 * INVG_) +
                                       expf(-d2 * INVG_) +
                                       expf(-d3 * INVG_));
            }
            r = __ldg(Drow + j) + sm;
        }
        nw[i] = r;
        if (t == 0) nw[0] = BIGV;
        res = r;
        __syncthreads();
        float* tmp = two; two = one; one = nw; nw = tmp;
    }
    if (t == N_ - 1) g_d[kb] = res;   // R[N, M]
}

// ============================================================
// Kernel 4: finalize scalar losses.
// ============================================================
__global__ void finalize_kernel(const int* __restrict__ mel_lens,
                                const int* __restrict__ src_lens,
                                const float* __restrict__ durations,
                                const float* __restrict__ mus,
                                const float* __restrict__ log_vars,
                                const int* __restrict__ step_p,
                                float* __restrict__ out) {
    __shared__ float red[256];
    int t = threadIdx.x;

    float kl = 0.f;
    for (int idx = t; idx < B_ * Z_; idx += 256) {
        float lv = log_vars[idx];
        float mu = mus[idx];
        kl += 1.f + lv - mu * mu - expf(lv);
    }
    red[t] = kl;
    __syncthreads();
    for (int s = 128; s; s >>= 1) {
        if (t < s) red[t] += red[t + s];
        __syncthreads();
    }

    if (t == 0) {
        float kl_loss = -0.5f * red[0];

        float sum_d = 0.f;
        for (int p = 0; p < KB_; p++) sum_d += g_d[p];
        float mel_iter_loss = sum_d / (float)B_;   // sum_k mean_b d

        float mel = 0.f, durl = 0.f;
        for (int b = 0; b < B_; b++) {
            float len = (float)mel_lens[b];
            mel += mel_iter_loss / ((float)K_ * len);
            float ds = 0.f;
            for (int s2 = 0; s2 < S_; s2++) ds += durations[b * S_ + s2];
            durl += fabsf(ds - len) / (float)src_lens[b];
        }
        mel  /= (float)B_;
        durl  = 2.f * durl / (float)B_;

        int step = step_p[0];
        float beta;
        if (step < 2000)       beta = 0.f;
        else if (step >= 8000) beta = 1.f;
        else                   beta = (float)(step - 2000) / 6000.f;

        float total = mel + durl + beta * kl_loss;
        out[0] = total;
        out[1] = mel;
        out[2] = durl;
        out[3] = kl_loss;
        out[4] = beta;
    }
}

// ============================================================
extern "C" void kernel_launch(void* const* d_in, const int* in_sizes, int n_in,
                              void* d_out, int out_size) {
    const float* mel_iters   = (const float*)d_in[0];
    const float* mel_targets = (const float*)d_in[1];
    const int*   mel_lens    = (const int*)  d_in[2];
    const int*   src_lens    = (const int*)  d_in[3];
    const float* durations   = (const float*)d_in[4];
    const float* mus         = (const float*)d_in[5];
    const float* log_vars    = (const float*)d_in[6];
    const int*   step        = (const int*)  d_in[7];
    float*       out         = (float*)d_out;

    (void)in_sizes; (void)n_in; (void)out_size;

    // 1) sigmoid + norms: one warp/row, 32000 rows, 8 warps/CTA
    const int total_rows = KB_ * N_ + B_ * N_;
    const int wpb = 8;
    prep_kernel<<<(total_rows + wpb - 1) / wpb, wpb * 32>>>(mel_iters, mel_targets);

    // 2) distance GEMM: 13x13 tiles x 32 pairs
    dim3 g((N_ + 63) / 64, (N_ + 63) / 64, KB_);
    dist_gemm_kernel<<<g, 256>>>();

    // 3) soft-DTW wavefront: one CTA per pair
    dtw_kernel<<<KB_, 800>>>();

    // 4) finalize
    finalize_kernel<<<1, 256>>>(mel_lens, src_lens, durations, mus, log_vars, step, out);
}